// round 1
// baseline (speedup 1.0000x reference)
#include <cuda_runtime.h>
#include <math.h>

#define B_ 4
#define C_ 32
#define L_ 256
#define M_ 256
#define F_ 8
#define N_ 64

typedef unsigned long long u64;

// Packed f32x2 FMA (sm_103a): d = a*b + c on two lanes at once.
__device__ __forceinline__ u64 ffma2(u64 a, u64 b, u64 c) {
    u64 d;
    asm("fma.rn.f32x2 %0, %1, %2, %3;" : "=l"(d) : "l"(a), "l"(b), "l"(c));
    return d;
}
__device__ __forceinline__ void upk(u64 v, float& x, float& y) {
    asm("mov.b64 {%0, %1}, %2;" : "=f"(x), "=f"(y) : "l"(v));
}

__global__ __launch_bounds__(128, 1) void sphere_conv_kernel(
    const float* __restrict__ xr, const float* __restrict__ xi,
    const float* __restrict__ wr, const float* __restrict__ wi,
    float* __restrict__ out)
{
    // Per-(f,c) interpolated weights, duplicated for f32x2: {wr, wr, wi, wi}
    __shared__ float4 w4s[F_ * C_];

    const int tid = threadIdx.x;
    const int bl  = blockIdx.x;        // b*L + l
    const int b   = bl >> 8;           // L_ == 256
    const int l   = bl & (L_ - 1);

    // interp_regular_1d_grid: t = l/(L-1)*(N-1); lo clipped to [0, N-2]
    const float t  = (float)(l * (N_ - 1)) / (float)(L_ - 1);
    int lo = (int)t;
    if (lo > N_ - 2) lo = N_ - 2;
    const float frac = t - (float)lo;
    const float om   = 1.0f - frac;

    // 256 (f,c) weight pairs filled by 128 threads (2 iters). w layout: (F,C,N,1).
    for (int i = tid; i < F_ * C_; i += 128) {
        const float wr0 = wr[i * N_ + lo], wr1 = wr[i * N_ + lo + 1];
        const float wi0 = wi[i * N_ + lo], wi1 = wi[i * N_ + lo + 1];
        const float wrv = wr0 * om + wr1 * frac;
        const float wiv = wi0 * om + wi1 * frac;
        w4s[i] = make_float4(wrv, wrv, wiv, wiv);
    }
    __syncthreads();

    const unsigned int saddr = (unsigned int)__cvta_generic_to_shared(w4s);

    // Split-sign accumulators: pr = prA - prB avoids packed negation in the loop.
    u64 prA[F_], prB[F_], pim[F_];
#pragma unroll
    for (int f = 0; f < F_; ++f) { prA[f] = 0ull; prB[f] = 0ull; pim[f] = 0ull; }

    // x index: ((b*C + c)*L + l)*M + m ; thread owns m = {2*tid, 2*tid+1}
    const int base = b * (C_ * L_ * M_) + l * M_ + 2 * tid;
    const float* xr_p = xr + base;
    const float* xi_p = xi + base;

#pragma unroll 4
    for (int c = 0; c < C_; ++c) {
        const u64 x_r = *(const u64*)(xr_p + c * (L_ * M_));
        const u64 x_i = *(const u64*)(xi_p + c * (L_ * M_));
#pragma unroll
        for (int f = 0; f < F_; ++f) {
            u64 wr2, wi2;
            asm("ld.shared.v2.u64 {%0, %1}, [%2];"
                : "=l"(wr2), "=l"(wi2)
                : "r"(saddr + (unsigned)((f * C_ + c) * 16)));
            prA[f] = ffma2(wr2, x_r, prA[f]);   // Σ wr*xr
            prB[f] = ffma2(wi2, x_i, prB[f]);   // Σ wi*xi
            pim[f] = ffma2(wr2, x_i, pim[f]);   // Σ wr*xi
            pim[f] = ffma2(wi2, x_r, pim[f]);   //   + wi*xr
        }
    }

    // scale = sqrt(1+l), mean over C folded in; relu on real part only.
    const float s  = sqrtf(1.0f + (float)l) * (1.0f / (float)C_);
    const int  m0  = 2 * tid;
    float2* outp   = (float2*)out;
    // out real at ((b*F+f)*L + l)*M + m ; imag offset B*F*L*M
    const int ob   = (b * F_ * L_ + l) * M_ + m0;
#pragma unroll
    for (int f = 0; f < F_; ++f) {
        float a0, a1, s0, s1, c0, c1;
        upk(prA[f], a0, a1);
        upk(prB[f], s0, s1);
        upk(pim[f], c0, c1);
        const float yr0 = fmaxf((a0 - s0) * s, 0.0f);
        const float yr1 = fmaxf((a1 - s1) * s, 0.0f);
        const float yi0 = c0 * s;
        const float yi1 = c1 * s;
        const int idx = ob + f * (L_ * M_);
        outp[idx >> 1]                              = make_float2(yr0, yr1);
        outp[(idx + B_ * F_ * L_ * M_) >> 1]        = make_float2(yi0, yi1);
    }
}

extern "C" void kernel_launch(void* const* d_in, const int* in_sizes, int n_in,
                              void* d_out, int out_size) {
    (void)in_sizes; (void)n_in; (void)out_size;
    sphere_conv_kernel<<<B_ * L_, 128>>>(
        (const float*)d_in[0], (const float*)d_in[1],
        (const float*)d_in[2], (const float*)d_in[3],
        (float*)d_out);
}

// round 3
// speedup vs baseline: 1.0097x; 1.0097x over previous
#include <cuda_runtime.h>
#include <math.h>

#define B_ 4
#define C_ 32
#define L_ 256
#define M_ 256
#define F_ 8
#define N_ 64
#define GRID_ 512          // each CTA handles 2 (b,l) pairs -> single wave
#define CL_ (L_ * M_)      // c-stride in x

typedef unsigned long long u64;

// Packed f32x2 FMA (sm_103a): d = a*b + c on two lanes at once.
__device__ __forceinline__ u64 ffma2(u64 a, u64 b, u64 c) {
    u64 d;
    asm("fma.rn.f32x2 %0, %1, %2, %3;" : "=l"(d) : "l"(a), "l"(b), "l"(c));
    return d;
}
__device__ __forceinline__ void upk(u64 v, float& x, float& y) {
    asm("mov.b64 {%0, %1}, %2;" : "=f"(x), "=f"(y) : "l"(v));
}
// Flip sign of both f32 lanes (2x LOP3 on the mostly-idle ALU pipe).
__device__ __forceinline__ u64 neg2(u64 v) {
    u64 d;
    asm("{\n\t"
        ".reg .b32 lo, hi;\n\t"
        "mov.b64 {lo, hi}, %1;\n\t"
        "xor.b32 lo, lo, 0x80000000;\n\t"
        "xor.b32 hi, hi, 0x80000000;\n\t"
        "mov.b64 %0, {lo, hi};\n\t"
        "}" : "=l"(d) : "l"(v));
    return d;
}

__global__ __launch_bounds__(128, 5) void sphere_conv_kernel(
    const float* __restrict__ xr, const float* __restrict__ xi,
    const float* __restrict__ wr, const float* __restrict__ wi,
    float* __restrict__ out)
{
    // layout [c][f]: {wr, wr, wi, wi} per (f,c), 16B each
    __shared__ float4 w4s[C_ * F_];

    const int tid = threadIdx.x;
    const unsigned int saddr = (unsigned int)__cvta_generic_to_shared(w4s);

    for (int half = 0; half < 2; ++half) {
        const int bl = blockIdx.x + half * GRID_;   // b*L + l
        const int b  = bl >> 8;                     // L_ == 256
        const int l  = bl & (L_ - 1);

        // interp_regular_1d_grid: t = l/(L-1)*(N-1); lo clipped to [0, N-2]
        const float t = (float)(l * (N_ - 1)) * (1.0f / (float)(L_ - 1));
        int lo = (int)t;
        if (lo > N_ - 2) lo = N_ - 2;
        const float frac = t - (float)lo;
        const float om   = 1.0f - frac;

        if (half) __syncthreads();   // everyone done reading previous weights
        for (int i = tid; i < F_ * C_; i += 128) {
            const int f = i & (F_ - 1);
            const int c = i >> 3;
            const int wix = (f * C_ + c) * N_ + lo;  // w layout (F,C,N,1)
            const float wrv = wr[wix] * om + wr[wix + 1] * frac;
            const float wiv = wi[wix] * om + wi[wix + 1] * frac;
            w4s[c * F_ + f] = make_float4(wrv, wrv, wiv, wiv);
        }
        __syncthreads();

        u64 pr[F_], pi[F_];
#pragma unroll
        for (int f = 0; f < F_; ++f) { pr[f] = 0ull; pi[f] = 0ull; }

        // thread owns m = {2*tid, 2*tid+1}
        const int base = b * (C_ * CL_) + l * M_ + 2 * tid;
        const float* xrp = xr + base;
        const float* xip = xi + base;

        // Software-pipelined over c: double-buffered groups of 4 c's
        u64 bxr[2][4], bxi[2][4];
#pragma unroll
        for (int j = 0; j < 4; ++j) {
            bxr[0][j] = *(const u64*)(xrp + j * CL_);
            bxi[0][j] = *(const u64*)(xip + j * CL_);
        }
        unsigned int soff = saddr;   // walks c*F_*16 linearly
#pragma unroll
        for (int cb = 0; cb < 8; ++cb) {
            const int cur = cb & 1, nxt = cur ^ 1;
            if (cb < 7) {
#pragma unroll
                for (int j = 0; j < 4; ++j) {
                    bxr[nxt][j] = *(const u64*)(xrp + ((cb + 1) * 4 + j) * CL_);
                    bxi[nxt][j] = *(const u64*)(xip + ((cb + 1) * 4 + j) * CL_);
                }
            }
#pragma unroll
            for (int j = 0; j < 4; ++j) {
                const u64 x_r = bxr[cur][j];
                const u64 x_i = bxi[cur][j];
                const u64 nxi = neg2(x_i);
#pragma unroll
                for (int f = 0; f < F_; ++f) {
                    u64 wrr, wii;
                    asm("ld.shared.v2.u64 {%0, %1}, [%2];"
                        : "=l"(wrr), "=l"(wii)
                        : "r"(soff + (unsigned)(f * 16)));
                    pr[f] = ffma2(wrr, x_r, pr[f]);   // + wr*xr
                    pr[f] = ffma2(wii, nxi, pr[f]);   // - wi*xi
                    pi[f] = ffma2(wii, x_r, pi[f]);   // + wi*xr
                    pi[f] = ffma2(wrr, x_i, pi[f]);   // + wr*xi
                }
                soff += F_ * 16;                      // next c
            }
        }

        // scale = sqrt(1+l)/C ; relu on real part only
        const float s  = sqrtf(1.0f + (float)l) * (1.0f / (float)C_);
        const int  m0  = 2 * tid;
        float2* outp   = (float2*)out;
        const int ob   = (b * F_ * L_ + l) * M_ + m0;
#pragma unroll
        for (int f = 0; f < F_; ++f) {
            float r0, r1, i0, i1;
            upk(pr[f], r0, r1);
            upk(pi[f], i0, i1);
            const int idx = ob + f * (L_ * M_);
            outp[idx >> 1] = make_float2(fmaxf(r0 * s, 0.0f), fmaxf(r1 * s, 0.0f));
            outp[(idx + B_ * F_ * L_ * M_) >> 1] = make_float2(i0 * s, i1 * s);
        }
    }
}

extern "C" void kernel_launch(void* const* d_in, const int* in_sizes, int n_in,
                              void* d_out, int out_size) {
    (void)in_sizes; (void)n_in; (void)out_size;
    sphere_conv_kernel<<<GRID_, 128>>>(
        (const float*)d_in[0], (const float*)d_in[1],
        (const float*)d_in[2], (const float*)d_in[3],
        (float*)d_out);
}